// round 16
// baseline (speedup 1.0000x reference)
#include <cuda_runtime.h>
#include <cuda_bf16.h>
#include <math.h>

typedef unsigned long long ull;
typedef unsigned int u32;

#define NB 128
#define UNITS 1024
#define BATCH 32
#define TT 512
#define IND 512

// ---------------- static device scratch (allocation-free) ----------------
// g_xp layout (transposed): [(t*32 + b)][4096]  -> per-step contiguous slab
__device__ float    g_xp[(size_t)BATCH * TT * 4 * UNITS];
__device__ unsigned g_bar;
// h state as bf16 hi/lo splits, [batch][1024], double buffered
__device__ __nv_bfloat16 g_hh[2][BATCH * UNITS];
__device__ __nv_bfloat16 g_hl[2][BATCH * UNITS];
// bf16 hi/lo splits for the tensor-core xproj GEMM
__device__ __nv_bfloat16 g_Ah[(size_t)16384 * 512];
__device__ __nv_bfloat16 g_Al[(size_t)16384 * 512];
__device__ __nv_bfloat16 g_Wh[(size_t)512 * 4096];
__device__ __nv_bfloat16 g_Wl[(size_t)512 * 4096];

// ---------------- f32x2 helpers -------------------------------------------
__device__ __forceinline__ void fma2(ull& d, ull a, ull b) {
    asm("fma.rn.f32x2 %0, %1, %2, %0;" : "+l"(d) : "l"(a), "l"(b));
}
__device__ __forceinline__ void add2(ull& d, ull a) {
    asm("add.rn.f32x2 %0, %0, %1;" : "+l"(d) : "l"(a));
}
__device__ __forceinline__ ull splat2(float x) {
    ull r; asm("mov.b64 %0, {%1, %1};" : "=l"(r) : "f"(x)); return r;
}
__device__ __forceinline__ void unpack2(ull v, float& lo, float& hi) {
    asm("mov.b64 {%0, %1}, %2;" : "=f"(lo), "=f"(hi) : "l"(v));
}

// ---------------- mma helpers ---------------------------------------------
__device__ __forceinline__ u32 smem_u32(const void* p) {
    return (u32)__cvta_generic_to_shared(p);
}
__device__ __forceinline__ void ldsm4(u32* r, u32 addr) {
    asm volatile("ldmatrix.sync.aligned.m8n8.x4.shared.b16 {%0,%1,%2,%3}, [%4];"
                 : "=r"(r[0]), "=r"(r[1]), "=r"(r[2]), "=r"(r[3]) : "r"(addr));
}
__device__ __forceinline__ void ldsm4t(u32* r, u32 addr) {
    asm volatile("ldmatrix.sync.aligned.m8n8.x4.trans.shared.b16 {%0,%1,%2,%3}, [%4];"
                 : "=r"(r[0]), "=r"(r[1]), "=r"(r[2]), "=r"(r[3]) : "r"(addr));
}
__device__ __forceinline__ void mma16816(float* cc, const u32* aa, u32 b0, u32 b1) {
    asm volatile(
        "mma.sync.aligned.m16n8k16.row.col.f32.bf16.bf16.f32 "
        "{%0,%1,%2,%3}, {%4,%5,%6,%7}, {%8,%9}, {%0,%1,%2,%3};"
        : "+f"(cc[0]), "+f"(cc[1]), "+f"(cc[2]), "+f"(cc[3])
        : "r"(aa[0]), "r"(aa[1]), "r"(aa[2]), "r"(aa[3]), "r"(b0), "r"(b1));
}

// ===================== init: zero h0 splits + barrier ====================
__global__ void init_kernel() {
    int i = blockIdx.x * blockDim.x + threadIdx.x;
    if (i == 0) g_bar = 0u;
    const __nv_bfloat16 z = __float2bfloat16(0.0f);
    for (int j = i; j < BATCH * UNITS; j += gridDim.x * blockDim.x) {
        g_hh[0][j] = z;
        g_hl[0][j] = z;
    }
}

// ===================== split: fp32 -> bf16 hi/lo =========================
__global__ void split_kernel(const float* __restrict__ A, const float* __restrict__ W) {
    int i = blockIdx.x * blockDim.x + threadIdx.x;
    int n = gridDim.x * blockDim.x;
    for (size_t j = i; j < (size_t)16384 * 512; j += n) {
        float v = A[j];
        __nv_bfloat16 hv = __float2bfloat16(v);
        g_Ah[j] = hv;
        g_Al[j] = __float2bfloat16(v - __bfloat162float(hv));
    }
    for (size_t j = i; j < (size_t)512 * 4096; j += n) {
        float v = W[j];
        __nv_bfloat16 hv = __float2bfloat16(v);
        g_Wh[j] = hv;
        g_Wl[j] = __float2bfloat16(v - __bfloat162float(hv));
    }
}

// ============ phase 1: tensor-core xproj (bf16 split, 3-MMA) ==============
#define PA 24
#define PB 136

__global__ __launch_bounds__(256) void xproj_mma(const float* __restrict__ bias) {
    __shared__ __nv_bfloat16 Ash[128 * PA];
    __shared__ __nv_bfloat16 Asl[128 * PA];
    __shared__ __nv_bfloat16 Bsh[16 * PB];
    __shared__ __nv_bfloat16 Bsl[16 * PB];

    const int tid = threadIdx.x;
    const int wid = tid >> 5;
    const int ln  = tid & 31;
    const int bm  = blockIdx.y << 7;
    const int bn  = blockIdx.x << 7;
    const int wm  = wid >> 2;
    const int wn  = wid & 3;

    float cfrag[4][4][4];
#pragma unroll
    for (int mi = 0; mi < 4; ++mi)
#pragma unroll
        for (int nj = 0; nj < 4; ++nj)
#pragma unroll
            for (int q = 0; q < 4; ++q) cfrag[mi][nj][q] = 0.0f;

    const int ar = tid >> 1;
    const int ac = (tid & 1) << 3;
    const int br = tid >> 4;
    const int bc = (tid & 15) << 3;
    const __nv_bfloat16* gAh = g_Ah + (size_t)(bm + ar) * 512 + ac;
    const __nv_bfloat16* gAl = g_Al + (size_t)(bm + ar) * 512 + ac;
    const __nv_bfloat16* gBh = g_Wh + (size_t)br * 4096 + bn + bc;
    const __nv_bfloat16* gBl = g_Wl + (size_t)br * 4096 + bn + bc;

    uint4 pah = *(const uint4*)gAh;
    uint4 pal = *(const uint4*)gAl;
    uint4 pbh = *(const uint4*)gBh;
    uint4 pbl = *(const uint4*)gBl;

    const int a_row  = ln & 15;
    const int a_col  = (ln >> 4) << 3;
    const int b_row  = (ln & 7) + (ln & 8);
    const int b_coln = (ln >> 4) << 3;

    for (int s = 0; s < 32; ++s) {
        *(uint4*)&Ash[ar * PA + ac] = pah;
        *(uint4*)&Asl[ar * PA + ac] = pal;
        *(uint4*)&Bsh[br * PB + bc] = pbh;
        *(uint4*)&Bsl[br * PB + bc] = pbl;
        __syncthreads();

        if (s < 31) {
            const int kk = (s + 1) << 4;
            pah = *(const uint4*)(gAh + kk);
            pal = *(const uint4*)(gAl + kk);
            pbh = *(const uint4*)(gBh + (size_t)kk * 4096);
            pbl = *(const uint4*)(gBl + (size_t)kk * 4096);
        }

        u32 ah[4][4];
        u32 al[4][4];
#pragma unroll
        for (int mi = 0; mi < 4; ++mi) {
            const int abase = ((wm << 6) + (mi << 4) + a_row) * PA + a_col;
            ldsm4(ah[mi], smem_u32(&Ash[abase]));
            ldsm4(al[mi], smem_u32(&Asl[abase]));
        }
        u32 bh[2][4];
        u32 bl[2][4];
#pragma unroll
        for (int bj = 0; bj < 2; ++bj) {
            const int bbase = b_row * PB + (wn << 5) + (bj << 4) + b_coln;
            ldsm4t(bh[bj], smem_u32(&Bsh[bbase]));
            ldsm4t(bl[bj], smem_u32(&Bsl[bbase]));
        }

#pragma unroll
        for (int mi = 0; mi < 4; ++mi) {
#pragma unroll
            for (int nj = 0; nj < 4; ++nj) {
                const int bj = nj >> 1;
                const int rr = (nj & 1) << 1;
                mma16816(cfrag[mi][nj], ah[mi], bh[bj][rr], bh[bj][rr + 1]);
                mma16816(cfrag[mi][nj], ah[mi], bl[bj][rr], bl[bj][rr + 1]);
                mma16816(cfrag[mi][nj], al[mi], bh[bj][rr], bh[bj][rr + 1]);
            }
        }
        __syncthreads();
    }

#pragma unroll
    for (int mi = 0; mi < 4; ++mi) {
#pragma unroll
        for (int nj = 0; nj < 4; ++nj) {
            const int row = bm + (wm << 6) + (mi << 4) + (ln >> 2);
            const int col = bn + (wn << 5) + (nj << 3) + ((ln & 3) << 1);
            const float bv0 = __ldg(&bias[col]);
            const float bv1 = __ldg(&bias[col + 1]);
            const size_t nr = (size_t)(((row & 511) << 5) + (row >> 9)) * 4096 + col;
            *(float2*)&g_xp[nr] =
                make_float2(cfrag[mi][nj][0] + bv0, cfrag[mi][nj][1] + bv1);
            *(float2*)&g_xp[nr + (size_t)256 * 4096] =
                make_float2(cfrag[mi][nj][2] + bv0, cfrag[mi][nj][3] + bv1);
        }
    }
}

// ============ phase 2: PERSISTENT tensor-core recurrence ==================
// 128 blocks x 512 threads, 1 block/SM. Block owns 32 gate-cols
// (col c: unit=c>>2, gate=c&3; colg(c)=(c&3)*1024+blk*8+(c>>2)).
// U as bf16 hi/lo in smem [1024][P2B=40] (ldmatrix conflict-free).
// 16 warps = 16-way split-K (64 k each = 4 ksteps of m16n8k16).
// A (h) fragments loaded per-lane from g_hh/g_hl [batch][1024] via __ldcg.
// Exchange zf: float2[(w*16+j)*32 + (b ^ ((j&3)<<3))], j = colpair 0..15.
#define P2B       40
#define UBL_OFF   81920
#define ZF_OFF    163840
#define LSTM_SMEM 229376

__global__ void __launch_bounds__(512, 1) lstm_kernel(const float* __restrict__ U,
                                                      float* __restrict__ outp) {
    extern __shared__ unsigned char sm[];
    __nv_bfloat16* Ubh = (__nv_bfloat16*)sm;
    __nv_bfloat16* Ubl = (__nv_bfloat16*)(sm + UBL_OFF);
    float2*        zf  = (float2*)(sm + ZF_OFF);

    const int tid = threadIdx.x;
    const int blk = blockIdx.x;
    const int w   = tid >> 5;
    const int ln  = tid & 31;
    const int r   = ln >> 2;
    const int c2  = (ln & 3) << 1;
    const int b_row  = (ln & 7) + (ln & 8);
    const int b_coln = (ln >> 4) << 3;
    const int k0w = w << 6;

    // ---- stage U bf16 hi/lo into smem ONCE ----
    {
        const int sc = tid & 31;
        const int sr = tid >> 5;
        const size_t colg = (size_t)((sc & 3) << 10) + (blk << 3) + (sc >> 2);
        for (int it = 0; it < 64; ++it) {
            int k = sr + (it << 4);
            float v = __ldg(&U[((size_t)k << 12) + colg]);
            __nv_bfloat16 hv = __float2bfloat16(v);
            Ubh[k * P2B + sc] = hv;
            Ubl[k * P2B + sc] = __float2bfloat16(v - __bfloat162float(hv));
        }
    }

    // reducer identity (tid < 256): unit w (0..7), batch ln
    const int bf = ln;
    const int ug = (blk << 3) + w;
    const int j0 = w << 1;
    const int j1 = j0 + 1;
    const int roff0 = (j0 << 5) + (bf ^ ((j0 & 3) << 3));
    const int roff1 = (j1 << 5) + (bf ^ ((j1 & 3) << 3));
    float creg = 0.0f;

    __syncthreads();

    for (int t = 0; t < TT; ++t) {
        const int cur = t & 1;
        const __nv_bfloat16* hh = g_hh[cur];
        const __nv_bfloat16* hl = g_hl[cur];

        // xp prefetch (reducers; consumed after the GEMM)
        float xpi = 0.f, xpf = 0.f, xpg = 0.f, xpo = 0.f;
        if (tid < 256) {
            const size_t btrow = ((size_t)((t << 5) + bf)) << 12;
            xpi = __ldg(&g_xp[btrow + ug]);
            xpf = __ldg(&g_xp[btrow + 1024 + ug]);
            xpg = __ldg(&g_xp[btrow + 2048 + ug]);
            xpo = __ldg(&g_xp[btrow + 3072 + ug]);
        }

        float cf[2][4][4];
#pragma unroll
        for (int mi = 0; mi < 2; ++mi)
#pragma unroll
            for (int nj = 0; nj < 4; ++nj)
#pragma unroll
                for (int q = 0; q < 4; ++q) cf[mi][nj][q] = 0.0f;

#pragma unroll
        for (int ks = 0; ks < 4; ++ks) {
            const int kk = k0w + (ks << 4);
            // A fragments from L2 (coherent): documented m16n8k16 A map
            u32 ah[2][4];
            u32 al[2][4];
#pragma unroll
            for (int mi = 0; mi < 2; ++mi) {
                const int base = (((mi << 4) + r) << 10) + kk + c2;
                ah[mi][0] = __ldcg((const u32*)(hh + base));
                ah[mi][1] = __ldcg((const u32*)(hh + base + (8 << 10)));
                ah[mi][2] = __ldcg((const u32*)(hh + base + 8));
                ah[mi][3] = __ldcg((const u32*)(hh + base + (8 << 10) + 8));
                al[mi][0] = __ldcg((const u32*)(hl + base));
                al[mi][1] = __ldcg((const u32*)(hl + base + (8 << 10)));
                al[mi][2] = __ldcg((const u32*)(hl + base + 8));
                al[mi][3] = __ldcg((const u32*)(hl + base + (8 << 10) + 8));
            }
            // B fragments from smem (phase-1-proven recipe)
            u32 bh0[4], bh1[4], bl0[4], bl1[4];
            const int bb = (kk + b_row) * P2B + b_coln;
            ldsm4t(bh0, smem_u32(&Ubh[bb]));
            ldsm4t(bh1, smem_u32(&Ubh[bb + 16]));
            ldsm4t(bl0, smem_u32(&Ubl[bb]));
            ldsm4t(bl1, smem_u32(&Ubl[bb + 16]));

#pragma unroll
            for (int mi = 0; mi < 2; ++mi) {
#pragma unroll
                for (int nj = 0; nj < 4; ++nj) {
                    const u32* Bh = (nj >> 1) ? bh1 : bh0;
                    const u32* Bl = (nj >> 1) ? bl1 : bl0;
                    const int rr = (nj & 1) << 1;
                    mma16816(cf[mi][nj], ah[mi], Bh[rr], Bh[rr + 1]);
                    mma16816(cf[mi][nj], ah[mi], Bl[rr], Bl[rr + 1]);
                    mma16816(cf[mi][nj], al[mi], Bh[rr], Bh[rr + 1]);
                }
            }
        }

        // ---- exchange: swizzled float2 partials ----
#pragma unroll
        for (int mi = 0; mi < 2; ++mi) {
#pragma unroll
            for (int nj = 0; nj < 4; ++nj) {
                const int j = (nj << 2) + (ln & 3);
                const int xo = (j & 3) << 3;
                const int bA = (mi << 4) + r;
                zf[(w << 9) + (j << 5) + (bA ^ xo)] =
                    make_float2(cf[mi][nj][0], cf[mi][nj][1]);
                zf[(w << 9) + (j << 5) + ((bA + 8) ^ xo)] =
                    make_float2(cf[mi][nj][2], cf[mi][nj][3]);
            }
        }
        __syncthreads();

        // ---- reduce + pointwise (tid < 256) ----
        if (tid < 256) {
            ull s0 = 0ull;
            ull s1 = 0ull;
            const ull* zp = (const ull*)zf;
#pragma unroll
            for (int wi = 0; wi < 16; ++wi) {
                add2(s0, zp[(wi << 9) + roff0]);
                add2(s1, zp[(wi << 9) + roff1]);
            }
            float zi, zfv, zg, zo;
            unpack2(s0, zi, zfv);
            unpack2(s1, zg, zo);
            zi += xpi;
            zfv += xpf;
            zg += xpg;
            zo += xpo;

            float ig = 1.0f / (1.0f + __expf(-zi));
            float fg = 1.0f / (1.0f + __expf(-zfv));
            float gv = 1.0f - 2.0f / (1.0f + __expf(2.0f * zg));
            float og = 1.0f / (1.0f + __expf(-zo));

            creg = fg * creg + ig * gv;
            float tanc = 1.0f - 2.0f / (1.0f + __expf(2.0f * creg));
            float hout = og * tanc;

            __nv_bfloat16 hhi = __float2bfloat16(hout);
            g_hh[cur ^ 1][(bf << 10) + ug] = hhi;
            g_hl[cur ^ 1][(bf << 10) + ug] =
                __float2bfloat16(hout - __bfloat162float(hhi));
            outp[(((size_t)((bf << 9) | t)) << 10) + ug] = hout;
        }

        if (t < TT - 1) {
            __syncthreads();
            if (tid == 0) {
                asm volatile("red.release.gpu.global.add.u32 [%0], %1;"
                             :: "l"(&g_bar), "r"(1u) : "memory");
                const unsigned target = (unsigned)(t + 1) * NB;
                unsigned v;
                unsigned spins = 0;
                do {
                    asm volatile("ld.acquire.gpu.global.u32 %0, [%1];"
                                 : "=r"(v) : "l"(&g_bar) : "memory");
                } while (v < target && ++spins < 0x40000000u);
            }
            __syncthreads();
        }
    }
}

// ========================= launcher ======================================
extern "C" void kernel_launch(void* const* d_in, const int* in_sizes, int n_in,
                              void* d_out, int out_size) {
    const float* inputs = (const float*)d_in[0];
    const float* W      = (const float*)d_in[1];
    const float* U      = (const float*)d_in[2];
    const float* bias   = (const float*)d_in[3];
    float* outp = (float*)d_out;

    cudaFuncSetAttribute(lstm_kernel,
                         cudaFuncAttributeMaxDynamicSharedMemorySize, LSTM_SMEM);

    init_kernel<<<64, 256>>>();
    split_kernel<<<256, 256>>>(inputs, W);
    dim3 g1(32, 128);
    xproj_mma<<<g1, 256>>>(bias);
    lstm_kernel<<<NB, 512, LSTM_SMEM>>>(U, outp);
}